// round 12
// baseline (speedup 1.0000x reference)
#include <cuda_runtime.h>
#include <cstdint>

// Beamform_1649267442279 — GB300 sm_103a — R12: R11's 4-stage pipeline had a
// buffer-ring bug (buf cycled mod 4 but refills rewrote the just-consumed
// buffer -> buffer 3 never written, every 4th tile garbage). Fix: 3-buffer
// ring; iteration k consumes buf k%3 and refills tile k+3 into buf k%3,
// which is exactly what iteration k+3 reads. wait_group 2 with 3 pending
// groups -> 2 full tiles (20KB/CTA) in flight during every compute phase;
// 5 CTAs/SM -> ~100KB/SM outstanding.
//
// Semantics: per channel s, blocks of 20 complex samples (40 floats).
// Block b, row r (0..3), col c (0..4):
//   re[r,c] = in_s[40b + 10r + 2c],  im[r,c] = in_s[40b + 10r + 2c + 1]
//   out[(s*Bc+b)*10 + c]     = sum_r br[r]*re - bi[r]*im
//   out[(s*Bc+b)*10 + 5 + c] = sum_r bi[r]*re + br[r]*im
// with br[r]=bf[2r], bi[r]=bf[2r+1].

#define THREADS      320
#define TILE_BLOCKS  64                     // beam blocks per tile
#define TILE_F4      (TILE_BLOCKS * 10)     // 640 float4 = 10240 B
#define F4_PER_THR   (TILE_F4 / THREADS)    // 2
#define STAGES       3

__device__ __forceinline__ void cp_async16(uint32_t saddr, const void* gptr) {
    asm volatile("cp.async.cg.shared.global [%0], [%1], 16;\n"
                 :: "r"(saddr), "l"(gptr));
}
__device__ __forceinline__ void cp_commit() {
    asm volatile("cp.async.commit_group;\n" ::: "memory");
}
__device__ __forceinline__ void cp_wait2() {
    asm volatile("cp.async.wait_group 2;\n" ::: "memory");
}

__global__ void __launch_bounds__(THREADS, 5)
beamform_kernel(const float* __restrict__ in0,
                const float* __restrict__ in1,
                const float* __restrict__ in2,
                const float* __restrict__ in3,
                const float* __restrict__ bf,
                float* __restrict__ out,
                int tiles_per_ch,     // ceil(Bc / TILE_BLOCKS)
                int blocks_per_ch,    // Bc
                int n_f4_per_ch)      // N / 4 float4 per channel
{
    __shared__ float4 s_in[STAGES][TILE_F4];     // 3 x 10240 B = 30 KB

    const int t  = threadIdx.x;
    const int ch = blockIdx.y;
    const float* __restrict__ in =
        (ch == 0) ? in0 : (ch == 1) ? in1 : (ch == 2) ? in2 : in3;

    const float4 w0 = __ldg((const float4*)bf);      // br0, bi0, br1, bi1
    const float4 w1 = __ldg((const float4*)bf + 1);  // br2, bi2, br3, bi3

    const uint32_t sbase = (uint32_t)__cvta_generic_to_shared(&s_in[0][0]);
    const int stride = gridDim.x;

    // thread -> (block-in-tile, column), fixed for all tiles
    const int b_loc = t / 5;
    const int j     = t - b_loc * 5;

    auto issue = [&](int tl, int buf) {
        const int f4_base = tl * TILE_F4;
        const float4* __restrict__ gsrc = (const float4*)in + f4_base;
        const uint32_t sb = sbase + (uint32_t)buf * (TILE_F4 * 16u)
                                  + (uint32_t)t * 16u;
        #pragma unroll
        for (int q = 0; q < F4_PER_THR; q++) {
            const int idx = t + q * THREADS;
            if (f4_base + idx < n_f4_per_ch)
                cp_async16(sb + (uint32_t)q * (THREADS * 16u), gsrc + idx);
        }
    };

    // ---- prologue: fill all 3 stages (3 committed groups) ----
    #pragma unroll
    for (int s = 0; s < STAGES; s++) {
        const int tl = blockIdx.x + s * stride;
        if (tl < tiles_per_ch) issue(tl, s);
        cp_commit();                       // one group per stage (may be empty)
    }

    int buf = 0;
    for (int tile = blockIdx.x; tile < tiles_per_ch; tile += stride) {
        cp_wait2();                        // oldest of 3 pending groups done
        __syncthreads();                   // smem visibility across threads

        // ---- compute: one task per thread ----
        const int b_glob = tile * TILE_BLOCKS + b_loc;
        if (b_glob < blocks_per_ch) {
            const float2* __restrict__ s2 = (const float2*)&s_in[buf][0];
            const int base = b_loc * 20 + j;
            const float2 v0 = s2[base];
            const float2 v1 = s2[base + 5];
            const float2 v2 = s2[base + 10];
            const float2 v3 = s2[base + 15];

            float re = w0.x * v0.x - w0.y * v0.y;
            float im = w0.y * v0.x + w0.x * v0.y;
            re += w0.z * v1.x - w0.w * v1.y;
            im += w0.w * v1.x + w0.z * v1.y;
            re += w1.x * v2.x - w1.y * v2.y;
            im += w1.y * v2.x + w1.x * v2.y;
            re += w1.z * v3.x - w1.w * v3.y;
            im += w1.w * v3.x + w1.z * v3.y;

            const size_t ob = ((size_t)ch * blocks_per_ch + (size_t)b_glob) * 10;
            __stcs(out + ob + j,     re);
            __stcs(out + ob + 5 + j, im);
        }
        __syncthreads();                   // all reads of buf done before refill

        const int nxt = tile + STAGES * stride;   // consumed at iter k+3, buf k%3
        if (nxt < tiles_per_ch) issue(nxt, buf);
        cp_commit();

        buf = (buf + 1 == STAGES) ? 0 : buf + 1;
    }
}

extern "C" void kernel_launch(void* const* d_in, const int* in_sizes, int n_in,
                              void* d_out, int out_size)
{
    const float* in0 = (const float*)d_in[0];
    const float* in1 = (const float*)d_in[1];
    const float* in2 = (const float*)d_in[2];
    const float* in3 = (const float*)d_in[3];
    const float* bf  = (const float*)d_in[4];
    float* out = (float*)d_out;

    const int N  = in_sizes[0];                        // 20,000,000 floats / ch
    const int Bc = N / 40;                             // 500,000 blocks / ch
    const int tiles = (Bc + TILE_BLOCKS - 1) / TILE_BLOCKS;  // 7813

    // 148 SMs x 5 CTAs/SM = 740 resident CTAs; grid (185, 4) = 740.
    dim3 grid(185, 4);
    beamform_kernel<<<grid, THREADS>>>(in0, in1, in2, in3, bf, out,
                                       tiles, Bc, N / 4);
}